// round 17
// baseline (speedup 1.0000x reference)
#include <cuda_runtime.h>
#include <cuda_fp16.h>
#include <math.h>
#include <stdint.h>

// Fixed shapes: B=8, S=4096, D=1024, H=16, hd=64
#define MTOT  32768
#define DDIM  1024
#define N_QKV 3072
#define NHEAD 16
#define HDIM  64

// GEMM tiling: BM=BN=128, BK=64 (2 x 32-wide sub-tiles), 4 warps (64x64 each),
// 2-stage cp.async pipeline, ONE __syncthreads per 64-wide chunk.
#define ROW_B    80                  // padded smem row: 40 halves = 80 bytes
#define ATILE_B  (128 * ROW_B)       // 10240
#define SUB_B    (2 * ATILE_B)       // 20480: one 32-wide sub-chunk (A + B)
#define STAGE_B  (2 * SUB_B)         // 40960: BK=64 chunk (2 sub-chunks)
#define STAGES   2
#define SMEM_GEMM (STAGES * STAGE_B) // 81920

// ---------------- scratch (device globals; allocation-free) ----------------
__device__ __align__(16) __half g_xh  [(size_t)MTOT * DDIM];    // 64 MB
__device__ __align__(16) __half g_qkv [(size_t)MTOT * N_QKV];   // 192 MB
__device__ __align__(16) __half g_ah  [(size_t)MTOT * DDIM];    // 64 MB
__device__ __align__(16) __half g_wqh [(size_t)N_QKV * DDIM];   // [N,K] 6 MB
__device__ __align__(16) __half g_woh [(size_t)DDIM * DDIM];    // [N,K] 2 MB

// ---------------- PTX helpers (sm_80-level only; no 'a' features) ----------
__device__ __forceinline__ uint32_t smem_u32(const void* p) {
    uint32_t a;
    asm("{ .reg .u64 t; cvta.to.shared.u64 t, %1; cvt.u32.u64 %0, t; }"
        : "=r"(a) : "l"(p));
    return a;
}
__device__ __forceinline__ void cp16(uint32_t dst, const void* src) {
    asm volatile("cp.async.cg.shared.global [%0], [%1], 16;"
                 :: "r"(dst), "l"(src) : "memory");
}
#define CP_COMMIT() asm volatile("cp.async.commit_group;" ::: "memory")
#define CP_WAIT(n)  asm volatile("cp.async.wait_group %0;" :: "n"(n) : "memory")

#define LDSM_X4(r, addr) \
    asm volatile("ldmatrix.sync.aligned.m8n8.x4.shared.b16 {%0,%1,%2,%3}, [%4];" \
                 : "=r"((r)[0]), "=r"((r)[1]), "=r"((r)[2]), "=r"((r)[3]) \
                 : "r"(addr))

#define MMA16816(d, a, b0, b1) \
    asm volatile("mma.sync.aligned.m16n8k16.row.col.f32.f16.f16.f32 " \
                 "{%0,%1,%2,%3}, {%4,%5,%6,%7}, {%8,%9}, {%0,%1,%2,%3};" \
                 : "+f"((d)[0]), "+f"((d)[1]), "+f"((d)[2]), "+f"((d)[3]) \
                 : "r"((a)[0]), "r"((a)[1]), "r"((a)[2]), "r"((a)[3]), \
                   "r"(b0), "r"(b1))

// ---------------------------------------------------------------------------
// fp16 mma.sync GEMM: C[M,N] = A[M,K] @ B[N,K]^T + bias
// A row-major [M,K] fp16, B row-major [N,K] fp16 (pre-transposed weights).
// CTA tile 128x128, BK=64, 4 warps each 64x64, fp32 accumulators.
// 2-stage pipeline; barrier + wait cost amortized over 128 HMMAs per warp.
// ---------------------------------------------------------------------------
template<bool HALF_OUT>
__global__ __launch_bounds__(128, 2)
void mma_gemm(const __half* __restrict__ A, const __half* __restrict__ B,
              const float* __restrict__ bias, void* __restrict__ Cout,
              int N, int K)
{
    extern __shared__ __align__(16) char smem[];
    const uint32_t sbase = smem_u32(smem);
    const int tid = threadIdx.x;
    const int L = tid & 31;
    const int w = tid >> 5;
    const int wm = w >> 1;          // 0..1  (64-row slabs)
    const int wn = w & 1;           // 0..1  (64-col slabs)
    const int m0 = blockIdx.y * 128;
    const int n0 = blockIdx.x * 128;

    // cp.async plan (per 32-wide sub-chunk): 128 threads x 8 segments:
    // rows (tid>>2)+32*i, 16B segment (tid&3)
    const int lrow = tid >> 2;      // 0..31
    const int lseg = tid & 3;
    const __half* gA[4];
    const __half* gB[4];
    uint32_t sA[4], sB[4];
    #pragma unroll
    for (int i = 0; i < 4; i++) {
        const int r = lrow + 32 * i;
        gA[i] = A + (size_t)(m0 + r) * K + lseg * 8;
        gB[i] = B + (size_t)(n0 + r) * K + lseg * 8;
        sA[i] = (uint32_t)(r * ROW_B + lseg * 16);
        sB[i] = ATILE_B + sA[i];
    }

    // ldmatrix lane address offsets (bytes within a sub-chunk)
    const uint32_t a_off = (uint32_t)(((wm * 64 + (L & 15)) * 40 + (L >> 4) * 8) * 2);
    const uint32_t b_off = (uint32_t)(ATILE_B
        + ((wn * 64 + (L & 7) + ((L >> 4) & 1) * 8) * 40 + ((L >> 3) & 1) * 8) * 2);

    float acc[4][8][4];
    #pragma unroll
    for (int mf = 0; mf < 4; mf++)
        #pragma unroll
        for (int nf = 0; nf < 8; nf++)
            #pragma unroll
            for (int i = 0; i < 4; i++) acc[mf][nf][i] = 0.0f;

    const int NK = K >> 6;   // chunks of 64 (= 16 for K=1024)

    // Prologue: chunk 0 -> stage 0 (both sub-chunks, one group)
    {
        const uint32_t st = sbase;
        #pragma unroll
        for (int j = 0; j < 2; j++) {
            const uint32_t sb = st + j * SUB_B;
            const int ko = j * 32;
            #pragma unroll
            for (int i = 0; i < 4; i++) {
                cp16(sb + sA[i], gA[i] + ko);
                cp16(sb + sB[i], gB[i] + ko);
            }
        }
        CP_COMMIT();
    }

    for (int c = 0; c < NK; c++) {
        CP_WAIT(0);
        __syncthreads();   // chunk c resident; chunk c-1 consumed by all warps

        // Prefetch chunk c+1 into the other stage (freed by the barrier)
        if (c + 1 < NK) {
            const uint32_t st = sbase + ((c + 1) & 1) * STAGE_B;
            const int ko0 = (c + 1) * 64;
            #pragma unroll
            for (int j = 0; j < 2; j++) {
                const uint32_t sb = st + j * SUB_B;
                const int ko = ko0 + j * 32;
                #pragma unroll
                for (int i = 0; i < 4; i++) {
                    cp16(sb + sA[i], gA[i] + ko);
                    cp16(sb + sB[i], gB[i] + ko);
                }
            }
            CP_COMMIT();
        }

        // Compute chunk c: 2 sub-chunks x 2 ks-steps x (8 LDSM + 32 HMMA)
        const uint32_t stg = sbase + (c & 1) * STAGE_B;
        #pragma unroll
        for (int j = 0; j < 2; j++) {
            const uint32_t aB = stg + j * SUB_B + a_off;
            const uint32_t bB = stg + j * SUB_B + b_off;
            #pragma unroll
            for (int ks = 0; ks < 2; ks++) {
                uint32_t a[4][4], b[4][4];
                #pragma unroll
                for (int mf = 0; mf < 4; mf++)
                    LDSM_X4(a[mf], aB + mf * (16 * ROW_B) + ks * 32);
                #pragma unroll
                for (int np = 0; np < 4; np++)
                    LDSM_X4(b[np], bB + np * (16 * ROW_B) + ks * 32);
                #pragma unroll
                for (int mf = 0; mf < 4; mf++)
                    #pragma unroll
                    for (int nf = 0; nf < 8; nf++)
                        MMA16816(acc[mf][nf], a[mf],
                                 b[nf >> 1][(nf & 1) * 2], b[nf >> 1][(nf & 1) * 2 + 1]);
            }
        }
    }

    // Epilogue: bias + store (half2 or float2)
    const int r0 = m0 + wm * 64 + (L >> 2);
    const int cb = n0 + wn * 64 + (L & 3) * 2;
    #pragma unroll
    for (int nf = 0; nf < 8; nf++) {
        const int col = cb + nf * 8;
        const float bx = __ldg(bias + col);
        const float by = __ldg(bias + col + 1);
        #pragma unroll
        for (int mf = 0; mf < 4; mf++) {
            const int ra = r0 + mf * 16;
            const int rb = ra + 8;
            if (HALF_OUT) {
                __half* C = (__half*)Cout;
                __half2 h0 = __floats2half2_rn(acc[mf][nf][0] + bx, acc[mf][nf][1] + by);
                __half2 h1 = __floats2half2_rn(acc[mf][nf][2] + bx, acc[mf][nf][3] + by);
                *reinterpret_cast<__half2*>(C + (size_t)ra * N + col) = h0;
                *reinterpret_cast<__half2*>(C + (size_t)rb * N + col) = h1;
            } else {
                float* C = (float*)Cout;
                float2 f0 = make_float2(acc[mf][nf][0] + bx, acc[mf][nf][1] + by);
                float2 f1 = make_float2(acc[mf][nf][2] + bx, acc[mf][nf][3] + by);
                *reinterpret_cast<float2*>(C + (size_t)ra * N + col) = f0;
                *reinterpret_cast<float2*>(C + (size_t)rb * N + col) = f1;
            }
        }
    }
}

// ---------------------------------------------------------------------------
// fp32 -> fp16 convert (8 elems/thread, coalesced)
// ---------------------------------------------------------------------------
__global__ __launch_bounds__(256)
void split_kernel(const float* __restrict__ in, __half* __restrict__ out)
{
    const int i = blockIdx.x * 256 + threadIdx.x;
    const float4* in4 = reinterpret_cast<const float4*>(in);
    float4 a = in4[2 * i], b = in4[2 * i + 1];
    float v[8] = {a.x, a.y, a.z, a.w, b.x, b.y, b.z, b.w};
    __half h[8];
    #pragma unroll
    for (int j = 0; j < 8; j++) h[j] = __float2half_rn(v[j]);
    reinterpret_cast<uint4*>(out)[i] = *reinterpret_cast<uint4*>(h);
}

// ---------------------------------------------------------------------------
// W[K,N] fp32 -> transposed fp16 [N,K]
// ---------------------------------------------------------------------------
__global__ __launch_bounds__(256)
void wsplit_kernel(const float* __restrict__ W, __half* __restrict__ T,
                   int K, int N)
{
    __shared__ float t[32][33];
    const int n0 = blockIdx.x * 32, k0 = blockIdx.y * 32;
    const int tx = threadIdx.x & 31, ty = threadIdx.x >> 5;   // 32 x 8
    #pragma unroll
    for (int r = 0; r < 32; r += 8)
        t[ty + r][tx] = W[(size_t)(k0 + ty + r) * N + n0 + tx];
    __syncthreads();
    #pragma unroll
    for (int r = 0; r < 32; r += 8) {
        float v = t[tx][ty + r];
        T[(size_t)(n0 + ty + r) * K + k0 + tx] = __float2half_rn(v);
    }
}

// ---------------------------------------------------------------------------
// Per-token 16x16 cross-head attention, fp16 in -> fp16 out (fp32 compute).
// ---------------------------------------------------------------------------
__global__ __launch_bounds__(128)
void attn_kernel(const __half* __restrict__ qkv, __half* __restrict__ out)
{
    __shared__ float row[N_QKV];
    __shared__ float sc[NHEAD][NHEAD + 1];

    const int t = threadIdx.x;
    const size_t tok = blockIdx.x;
    const uint4* src = reinterpret_cast<const uint4*>(qkv + tok * (size_t)N_QKV);

    // Load 3072 halves -> fp32 smem (8 halves per uint4)
    for (int i = t; i < N_QKV / 8; i += 128) {
        uint4 v = src[i];
        const __half2* h = reinterpret_cast<const __half2*>(&v);
        #pragma unroll
        for (int j = 0; j < 4; j++) {
            float2 f = __half22float2(h[j]);
            row[i * 8 + j * 2 + 0] = f.x;
            row[i * 8 + j * 2 + 1] = f.y;
        }
    }
    __syncthreads();

    #pragma unroll
    for (int p = t; p < NHEAD * NHEAD; p += 128) {
        const int qh = p >> 4, kh = p & 15;
        const float* q  = row + qh * 192;
        const float* kk = row + kh * 192 + 64;
        float s = 0.0f;
        #pragma unroll
        for (int d = 0; d < HDIM; d++) s = fmaf(q[d], kk[d], s);
        sc[qh][kh] = s * 0.125f;   // 1/sqrt(64)
    }
    __syncthreads();

    if (t < NHEAD) {
        float m = sc[t][0];
        #pragma unroll
        for (int j = 1; j < NHEAD; j++) m = fmaxf(m, sc[t][j]);
        float sum = 0.0f;
        #pragma unroll
        for (int j = 0; j < NHEAD; j++) {
            float e = __expf(sc[t][j] - m);
            sc[t][j] = e; sum += e;
        }
        float inv = 1.0f / sum;
        #pragma unroll
        for (int j = 0; j < NHEAD; j++) sc[t][j] *= inv;
    }
    __syncthreads();

    const size_t ob = tok * (size_t)DDIM;
    #pragma unroll
    for (int o = t; o < DDIM; o += 128) {
        const int qh = o >> 6, d = o & 63;
        float a = 0.0f;
        #pragma unroll
        for (int kh = 0; kh < NHEAD; kh++)
            a = fmaf(sc[qh][kh], row[kh * 192 + 128 + d], a);
        out[ob + o] = __float2half_rn(a);
    }
}

// ---------------------------------------------------------------------------
extern "C" void kernel_launch(void* const* d_in, const int* in_sizes, int n_in,
                              void* d_out, int out_size)
{
    (void)in_sizes; (void)n_in; (void)out_size;
    const float* x     = (const float*)d_in[0];
    const float* W_qkv = (const float*)d_in[1];
    const float* b_qkv = (const float*)d_in[2];
    const float* W_out = (const float*)d_in[3];
    const float* b_out = (const float*)d_in[4];
    float* out = (float*)d_out;

    void *p_xh, *p_qkv, *p_ah, *p_wqh, *p_woh;
    cudaGetSymbolAddress(&p_xh,  g_xh);
    cudaGetSymbolAddress(&p_qkv, g_qkv);
    cudaGetSymbolAddress(&p_ah,  g_ah);
    cudaGetSymbolAddress(&p_wqh, g_wqh);
    cudaGetSymbolAddress(&p_woh, g_woh);

    cudaFuncSetAttribute(mma_gemm<true>,
                         cudaFuncAttributeMaxDynamicSharedMemorySize, SMEM_GEMM);
    cudaFuncSetAttribute(mma_gemm<false>,
                         cudaFuncAttributeMaxDynamicSharedMemorySize, SMEM_GEMM);

    // 1) x -> fp16
    split_kernel<<<(MTOT * DDIM) / 8 / 256, 256>>>(x, (__half*)p_xh);
    // 2) weights -> transposed fp16 [N,K]
    wsplit_kernel<<<dim3(N_QKV / 32, DDIM / 32), 256>>>(
        W_qkv, (__half*)p_wqh, DDIM, N_QKV);
    wsplit_kernel<<<dim3(DDIM / 32, DDIM / 32), 256>>>(
        W_out, (__half*)p_woh, DDIM, DDIM);
    // 3) GEMM1: qkv(fp16) = x @ W_qkv + b_qkv
    mma_gemm<true><<<dim3(N_QKV / 128, MTOT / 128), 128, SMEM_GEMM>>>(
        (const __half*)p_xh, (const __half*)p_wqh, b_qkv, p_qkv, N_QKV, DDIM);
    // 4) per-token attention (fp16 -> fp16)
    attn_kernel<<<MTOT, 128>>>((const __half*)p_qkv, (__half*)p_ah);
    // 5) GEMM2: out(fp32) = attn @ W_out + b_out
    mma_gemm<false><<<dim3(DDIM / 128, MTOT / 128), 128, SMEM_GEMM>>>(
        (const __half*)p_ah, (const __half*)p_woh, b_out, (void*)out, DDIM, DDIM);
}